// round 15
// baseline (speedup 1.0000x reference)
#include <cuda_runtime.h>
#include <cuda_fp16.h>
#include <math.h>
#include <stdint.h>

#define BATCH 4
#define TSEQ  2048
#define CCH   1024
#define NH    16
#define HS    64
#define MTOK  (BATCH*TSEQ)   // 8192
#define CC2   (CCH*CCH)

// ---------------------------------------------------------------------------
// Device-global scratch (fp16)
// ---------------------------------------------------------------------------
__device__ __half g_xh[MTOK*CCH];          // x, fp16
__device__ __half g_wh[4*CC2];             // Wq, Wk, Wv, Wp fp16
__device__ __half g_q[BATCH*NH*TSEQ*HS];   // [bh][t][d], PRE-SCALED by 0.125*log2e
__device__ __half g_k[BATCH*NH*TSEQ*HS];   // [bh][t][d]
__device__ __half g_vt[BATCH*NH*HS*TSEQ];  // [bh][d][t]  (TRANSPOSED)
__device__ __half g_att[MTOK*CCH];         // [b][t][c]

// ---------------------------------------------------------------------------
// Helpers
// ---------------------------------------------------------------------------
__device__ __forceinline__ void mma16(float* d,
                                      uint32_t a0, uint32_t a1, uint32_t a2, uint32_t a3,
                                      uint32_t b0, uint32_t b1)
{
    asm("mma.sync.aligned.m16n8k16.row.col.f32.f16.f16.f32 "
        "{%0,%1,%2,%3}, {%4,%5,%6,%7}, {%8,%9}, {%0,%1,%2,%3};\n"
        : "+f"(d[0]), "+f"(d[1]), "+f"(d[2]), "+f"(d[3])
        : "r"(a0), "r"(a1), "r"(a2), "r"(a3), "r"(b0), "r"(b1));
}

__device__ __forceinline__ void ldsm4(uint32_t* d, uint32_t addr) {
    asm volatile("ldmatrix.sync.aligned.m8n8.x4.shared.b16 {%0,%1,%2,%3}, [%4];"
        : "=r"(d[0]), "=r"(d[1]), "=r"(d[2]), "=r"(d[3]) : "r"(addr));
}

__device__ __forceinline__ float ex2(float x) {
    float y;
    asm("ex2.approx.f32 %0, %1;" : "=f"(y) : "f"(x));
    return y;
}

__device__ __forceinline__ uint32_t smem_u32(const void* p) {
    uint32_t a;
    asm("{ .reg .u64 t; cvta.to.shared.u64 t, %1; cvt.u32.u64 %0, t; }"
        : "=r"(a) : "l"(p));
    return a;
}

__device__ __forceinline__ void cpa16(uint32_t dst, const void* src) {
    asm volatile("cp.async.cg.shared.global [%0], [%1], 16;" :: "r"(dst), "l"(src));
}
__device__ __forceinline__ void cpa_commit() {
    asm volatile("cp.async.commit_group;" ::: "memory");
}
#define CPA_WAIT(N) asm volatile("cp.async.wait_group %0;" :: "n"(N) : "memory")

__device__ __forceinline__ void bar_sync(int id, int cnt) {
    asm volatile("bar.sync %0, %1;" :: "r"(id), "r"(cnt) : "memory");
}
__device__ __forceinline__ void bar_arrive(int id, int cnt) {
    asm volatile("bar.arrive %0, %1;" :: "r"(id), "r"(cnt) : "memory");
}

__device__ __forceinline__ uint32_t h2u(__half2 h) {
    return *(uint32_t*)&h;
}

#define QSCALE 0.180336881f      // 0.125 * log2(e)

// ---------------------------------------------------------------------------
// fp16 converter: x + all 4 weights, 4 float4s per thread (MLP=4)
// ---------------------------------------------------------------------------
#define XF4 (MTOK*CCH/4)         // 2,097,152
#define WF4 (CC2/4)              // 262,144
#define CF4 (XF4 + 4*WF4)        // 3,145,728 total float4s
#define CONV_BLOCKS (CF4/(256*4))

__global__ void __launch_bounds__(256) conv_all(const float* __restrict__ x,
                                                const float* __restrict__ wq,
                                                const float* __restrict__ wk,
                                                const float* __restrict__ wv,
                                                const float* __restrict__ wp)
{
    const int base = blockIdx.x * (256*4) + threadIdx.x;
    #pragma unroll
    for (int t = 0; t < 4; t++) {
        const int i = base + t * 256;
        float4 v;
        __half2* dst;
        if (i < XF4) {
            v = ((const float4*)x)[i];
            dst = (__half2*)g_xh + 2 * (size_t)i;
        } else {
            const int j = i - XF4;
            const int z = j / WF4;
            const int k = j - z * WF4;
            const float* s = (z == 0) ? wq : (z == 1) ? wk : (z == 2) ? wv : wp;
            v = ((const float4*)s)[k];
            dst = (__half2*)(g_wh + (size_t)z * CC2) + 2 * (size_t)k;
        }
        dst[0] = __floats2half2_rn(v.x, v.y);
        dst[1] = __floats2half2_rn(v.z, v.w);
    }
}

// ---------------------------------------------------------------------------
// Warp-specialized fp16 GEMM core: 288 threads.
//   warps 0-7: consumers (LDSM + MMA only), 4(M)x2(N), warp tile 32x64
//   warp 8:    producer (all cp.async; one stage ahead)
// Named barriers: full0/1 = 1/2, empty0/1 = 3/4 (count 288).
// BK=64 halfs, 2 stages, SMEM row = 64 halfs + pad = 36 words, 72KB.
// ---------------------------------------------------------------------------
#define BKH      64
#define GSTW     36
#define GSTGW    (128*GSTW)             // 4608 words per operand-stage
#define GEMM_SMEM (2*2*GSTGW*4)         // 73728 bytes
#define GTHREADS 288

__device__ __forceinline__ void gemm_core(const __half* __restrict__ A,
                                          const __half* __restrict__ B,
                                          float acc[2][8][4])
{
    extern __shared__ uint32_t smw[];
    const uint32_t a_base = smem_u32(smw);
    const uint32_t b_base = a_base + 2*GSTGW*4;

    const int tid  = threadIdx.x;
    const int lane = tid & 31;
    const int warp = tid >> 5;
    const int NIT  = CCH / BKH;         // 16

    if (warp == 8) {
        // ---------------- producer ----------------
        for (int it = 0; it < NIT; it++) {
            if (it >= 2) bar_sync(3 + (it & 1), GTHREADS);
            const uint32_t sa = a_base + (uint32_t)(it & 1) * (GSTGW*4);
            const uint32_t sb = b_base + (uint32_t)(it & 1) * (GSTGW*4);
            const size_t go = (size_t)it * BKH;
            #pragma unroll
            for (int t = 0; t < 4; t++) {
                const int row = lane + 32 * t;
                const __half* ag = A + (size_t)row * CCH + go;
                const __half* bg = B + (size_t)row * CCH + go;
                const uint32_t da = sa + (uint32_t)row * (GSTW*4);
                const uint32_t db = sb + (uint32_t)row * (GSTW*4);
                #pragma unroll
                for (int c = 0; c < 8; c++) {
                    cpa16(da + c*16, ag + c*8);
                    cpa16(db + c*16, bg + c*8);
                }
            }
            cpa_commit();
            CPA_WAIT(0);
            __threadfence_block();
            bar_arrive(1 + (it & 1), GTHREADS);
        }
    } else {
        // ---------------- consumers ----------------
        const int wm   = warp >> 1;     // 0..3
        const int wn   = warp & 1;      // 0..1
        const int mb   = wm * 32;
        const int nb   = wn * 64;
        const int arow = (lane & 7) + ((lane >> 3) & 1) * 8;
        const int akw  = ((lane >> 4) & 1) * 4;
        const int brow = (lane & 7) + ((lane >> 4) & 1) * 8;
        const int bkw  = ((lane >> 3) & 1) * 4;

        for (int it = 0; it < NIT; it++) {
            bar_sync(1 + (it & 1), GTHREADS);

            const uint32_t as_addr = a_base + (uint32_t)(it & 1) * (GSTGW*4);
            const uint32_t bs_addr = b_base + (uint32_t)(it & 1) * (GSTGW*4);

            #pragma unroll
            for (int ks = 0; ks < 4; ks++) {        // 4 x k16 per BK=64
                const int kk = ks * 8;
                uint32_t a[2][4], bfr[4][4];
                #pragma unroll
                for (int mf = 0; mf < 2; mf++)
                    ldsm4(a[mf], as_addr + ((uint32_t)(mb + mf*16 + arow) * GSTW + kk + akw) * 4);
                #pragma unroll
                for (int pf = 0; pf < 4; pf++)
                    ldsm4(bfr[pf], bs_addr + ((uint32_t)(nb + pf*16 + brow) * GSTW + kk + bkw) * 4);
                #pragma unroll
                for (int mf = 0; mf < 2; mf++)
                    #pragma unroll
                    for (int nf = 0; nf < 8; nf++)
                        mma16(acc[mf][nf], a[mf][0], a[mf][1], a[mf][2], a[mf][3],
                              bfr[nf >> 1][(nf & 1) * 2], bfr[nf >> 1][(nf & 1) * 2 + 1]);
            }
            bar_arrive(3 + (it & 1), GTHREADS);
        }
    }
}

// ---------------------------------------------------------------------------
// QKV GEMM: z=0 -> q (PRE-SCALED), z=1 -> k, z=2 -> v transposed
// ---------------------------------------------------------------------------
__global__ void __launch_bounds__(GTHREADS, 2) qkv_gemm()
{
    const int z  = blockIdx.z;
    const int m0 = blockIdx.y * 128;
    const int n0 = blockIdx.x * 128;

    float acc[2][8][4];
    #pragma unroll
    for (int i = 0; i < 2; i++)
        #pragma unroll
        for (int j = 0; j < 8; j++)
            #pragma unroll
            for (int c = 0; c < 4; c++) acc[i][j][c] = 0.f;

    gemm_core(g_xh + (size_t)m0 * CCH,
              g_wh + (size_t)z * CC2 + (size_t)n0 * CCH, acc);

    const int lane = threadIdx.x & 31;
    const int warp = threadIdx.x >> 5;
    if (warp >= 8) return;
    const int wm = warp >> 1, wn = warp & 1;
    const int g = lane >> 2, r = lane & 3;

    if (z < 2) {
        __half* out = (z == 0) ? g_q : g_k;
        const float sc = (z == 0) ? QSCALE : 1.0f;
        #pragma unroll
        for (int mf = 0; mf < 2; mf++) {
            const int row0 = m0 + wm * 32 + mf * 16 + g;
            #pragma unroll
            for (int nf = 0; nf < 8; nf++) {
                const int col = n0 + wn * 64 + nf * 8 + 2 * r;
                const int h = col >> 6, d = col & 63;
                {
                    const int b = row0 >> 11, t = row0 & 2047;
                    *(__half2*)&out[((size_t)(b * NH + h) * TSEQ + t) * HS + d] =
                        __floats2half2_rn(acc[mf][nf][0] * sc, acc[mf][nf][1] * sc);
                }
                {
                    const int row1 = row0 + 8;
                    const int b = row1 >> 11, t = row1 & 2047;
                    *(__half2*)&out[((size_t)(b * NH + h) * TSEQ + t) * HS + d] =
                        __floats2half2_rn(acc[mf][nf][2] * sc, acc[mf][nf][3] * sc);
                }
            }
        }
    } else {
        #pragma unroll
        for (int mf = 0; mf < 2; mf++) {
            const int row0 = m0 + wm * 32 + mf * 16 + g;
            const int b = row0 >> 11, t0 = row0 & 2047;
            #pragma unroll
            for (int nf = 0; nf < 8; nf++) {
                const int col = n0 + wn * 64 + nf * 8 + 2 * r;
                const int h = col >> 6, d = col & 63;
                __half* base = g_vt + ((size_t)(b * NH + h) * HS + d) * TSEQ;
                base[t0]            = __float2half_rn(acc[mf][nf][0]);
                base[TSEQ + t0]     = __float2half_rn(acc[mf][nf][1]);
                base[t0 + 8]        = __float2half_rn(acc[mf][nf][2]);
                base[TSEQ + t0 + 8] = __float2half_rn(acc[mf][nf][3]);
            }
        }
    }
}

// ---------------------------------------------------------------------------
// Output projection: out = g_att @ Wp^T + bp  (fp32 out)
// ---------------------------------------------------------------------------
__global__ void __launch_bounds__(GTHREADS, 2) proj_gemm(const float* __restrict__ bp,
                                                         float* __restrict__ out)
{
    const int m0 = blockIdx.y * 128;
    const int n0 = blockIdx.x * 128;

    float acc[2][8][4];
    #pragma unroll
    for (int i = 0; i < 2; i++)
        #pragma unroll
        for (int j = 0; j < 8; j++)
            #pragma unroll
            for (int c = 0; c < 4; c++) acc[i][j][c] = 0.f;

    gemm_core(g_att + (size_t)m0 * CCH,
              g_wh + (size_t)3 * CC2 + (size_t)n0 * CCH, acc);

    const int lane = threadIdx.x & 31;
    const int warp = threadIdx.x >> 5;
    if (warp >= 8) return;
    const int wm = warp >> 1, wn = warp & 1;
    const int g = lane >> 2, r = lane & 3;

    #pragma unroll
    for (int mf = 0; mf < 2; mf++) {
        const int row0 = m0 + wm * 32 + mf * 16 + g;
        #pragma unroll
        for (int nf = 0; nf < 8; nf++) {
            const int col = n0 + wn * 64 + nf * 8 + 2 * r;
            const float b0 = bp[col], b1 = bp[col + 1];
            *(float2*)&out[(size_t)row0 * CCH + col] =
                make_float2(acc[mf][nf][0] + b0, acc[mf][nf][1] + b1);
            *(float2*)&out[(size_t)(row0 + 8) * CCH + col] =
                make_float2(acc[mf][nf][2] + b0, acc[mf][nf][3] + b1);
        }
    }
}

// ---------------------------------------------------------------------------
// Causal flash attention: 256 threads = 8 warps, warp = 16 query rows x 64 keys.
// 128-key K/V tiles, double-buffered. Per-warp diagonal bound (jj < warp+1).
// (unchanged from R13)
// ---------------------------------------------------------------------------
#define KSTRW 36
#define VSTRW 68
#define KBUF  (128*KSTRW)                 // 4608 words
#define VBUF  (64*VSTRW)                  // 4352 words
#define F4K   0
#define F4V   (2*KBUF)
#define FLASH_SMEM ((2*KBUF + 2*VBUF)*4)  // 71680 bytes
#define HONES 0x3C003C00u                 // half2(1.0, 1.0)

__global__ void __launch_bounds__(256, 2) flash_kernel()
{
    extern __shared__ uint32_t smw[];
    const uint32_t sbase = smem_u32(smw);

    const int tid  = threadIdx.x;
    const int lane = tid & 31;
    const int warp = tid >> 5;          // 0..7
    const int mb   = warp * 16;         // 16 query rows per warp
    const int g    = lane >> 2;
    const int r    = lane & 3;

    const int krow = lane & 7;
    const int kkw  = (lane >> 3) * 4;
    const int brow = (lane & 7) + ((lane >> 4) & 1) * 8;
    const int bkw  = ((lane >> 3) & 1) * 4;

    const int qi = (int)gridDim.x - 1 - (int)blockIdx.x;   // heavy first
    const int bh = blockIdx.y;
    const int q0 = qi * 128;
    const __half* kbase = g_k  + (size_t)bh * TSEQ * HS;   // [t][d]
    const __half* vbase = g_vt + (size_t)bh * HS * TSEQ;   // [d][t]

    #pragma unroll
    for (int t = 0; t < 4; t++) {
        const int i = tid + t * 256;
        const int row = i >> 3, c = i & 7;
        cpa16(sbase + (F4K*4) + row * (KSTRW*4) + c * 16,
              kbase + (size_t)row * HS + c * 8);
    }
    #pragma unroll
    for (int t = 0; t < 4; t++) {
        const int i = tid + t * 256;
        const int row = i >> 4, c = i & 15;
        cpa16(sbase + (F4V*4) + row * (VSTRW*4) + c * 16,
              vbase + (size_t)row * TSEQ + c * 8);
    }
    cpa_commit();

    uint32_t q[4][4];
    {
        const uint32_t* gq = (const uint32_t*)g_q;
        const int row = q0 + mb + g;
        const uint32_t* q0p = gq + ((size_t)bh * TSEQ + row) * 32;
        const uint32_t* q1p = q0p + 8 * 32;
        #pragma unroll
        for (int st = 0; st < 4; st++) {
            q[st][0] = q0p[st * 8 + r];
            q[st][1] = q1p[st * 8 + r];
            q[st][2] = q0p[st * 8 + 4 + r];
            q[st][3] = q1p[st * 8 + 4 + r];
        }
    }

    float o[8][4];
    #pragma unroll
    for (int j = 0; j < 8; j++)
        #pragma unroll
        for (int c = 0; c < 4; c++) o[j][c] = 0.f;
    float lacc[4] = {0.f, 0.f, 0.f, 0.f};

    uint32_t ksub = sbase + (uint32_t)F4K * 4;
    uint32_t vsub = sbase + (uint32_t)F4V * 4;

    auto group = [&](int jj, bool masked) {
        uint32_t vb[4][4];
        #pragma unroll
        for (int pf = 0; pf < 4; pf++)
            ldsm4(vb[pf], vsub + ((uint32_t)(pf*16 + brow) * VSTRW + 8*jj + bkw) * 4);

        float s[2][4];
        #pragma unroll
        for (int jh = 0; jh < 2; jh++) {
            uint32_t kb[2][4];
            const uint32_t ka = ksub + ((uint32_t)(16*jj + 8*jh + krow) * KSTRW + kkw) * 4;
            ldsm4(kb[0], ka);
            ldsm4(kb[1], ka + 16 * 4);
            #pragma unroll
            for (int c = 0; c < 4; c++) s[jh][c] = 0.f;
            #pragma unroll
            for (int st = 0; st < 4; st++) {
                const uint32_t b0 = kb[st >> 1][(st & 1) * 2];
                const uint32_t b1 = kb[st >> 1][(st & 1) * 2 + 1];
                mma16(s[jh], q[st][0], q[st][1], q[st][2], q[st][3], b0, b1);
            }
        }

        if (masked) {
            #pragma unroll
            for (int jh = 0; jh < 2; jh++) {
                const int colb = 16*jj + 8*jh + 2*r;
                const int rwa = mb + g;
                if (colb     > rwa    ) s[jh][0] = -1e30f;
                if (colb + 1 > rwa    ) s[jh][1] = -1e30f;
                if (colb     > rwa + 8) s[jh][2] = -1e30f;
                if (colb + 1 > rwa + 8) s[jh][3] = -1e30f;
            }
        }

        uint32_t pA[4];
        #pragma unroll
        for (int jh = 0; jh < 2; jh++) {
            const float e0 = ex2(s[jh][0]);
            const float e1 = ex2(s[jh][1]);
            const float e2 = ex2(s[jh][2]);
            const float e3 = ex2(s[jh][3]);
            pA[jh*2    ] = h2u(__floats2half2_rn(e0, e1));
            pA[jh*2 + 1] = h2u(__floats2half2_rn(e2, e3));
        }

        mma16(lacc, pA[0], pA[1], pA[2], pA[3], HONES, HONES);

        #pragma unroll
        for (int nf = 0; nf < 8; nf++) {
            const uint32_t b0 = vb[nf >> 1][(nf & 1) * 2];
            const uint32_t b1 = vb[nf >> 1][(nf & 1) * 2 + 1];
            mma16(o[nf], pA[0], pA[1], pA[2], pA[3], b0, b1);
        }
    };

    const int nt = qi + 1;               // 128-key tiles
    for (int kt = 0; kt < nt; kt++) {
        __syncthreads();

        if (kt + 1 < nt) {
            const int b1 = (kt + 1) & 1;
            const __half* kg = kbase + (size_t)(kt + 1) * 128 * HS;
            const __half* vg = vbase + (size_t)(kt + 1) * 128;
            #pragma unroll
            for (int t = 0; t < 4; t++) {
                const int i = tid + t * 256;
                const int row = i >> 3, c = i & 7;
                cpa16(sbase + (F4K + b1*KBUF)*4 + row * (KSTRW*4) + c * 16,
                      kg + (size_t)row * HS + c * 8);
            }
            #pragma unroll
            for (int t = 0; t < 4; t++) {
                const int i = tid + t * 256;
                const int row = i >> 4, c = i & 15;
                cpa16(sbase + (F4V + b1*VBUF)*4 + row * (VSTRW*4) + c * 16,
                      vg + (size_t)row * TSEQ + c * 8);
            }
            cpa_commit();
            CPA_WAIT(1);
        } else {
            CPA_WAIT(0);
        }
        __syncthreads();

        const int b = kt & 1;
        ksub = sbase + (uint32_t)(F4K + b*KBUF) * 4;
        vsub = sbase + (uint32_t)(F4V + b*VBUF) * 4;

        if (kt < qi) {
            #pragma unroll
            for (int jj = 0; jj < 8; jj++) group(jj, false);
        } else {
            const int jmax = warp + 1;
            for (int jj = 0; jj < jmax; jj++) group(jj, true);
        }
    }

    const int b = bh >> 4, h = bh & 15;
    {
        const int row = mb + g;
        const float inv0 = 1.0f / lacc[0];
        const float inv1 = 1.0f / lacc[2];
        const int t0 = q0 + row, t1 = t0 + 8;
        #pragma unroll
        for (int nf = 0; nf < 8; nf++) {
            const int c = h * HS + nf * 8 + 2 * r;
            *(__half2*)&g_att[((size_t)b * TSEQ + t0) * CCH + c] =
                __floats2half2_rn(o[nf][0] * inv0, o[nf][1] * inv0);
            *(__half2*)&g_att[((size_t)b * TSEQ + t1) * CCH + c] =
                __floats2half2_rn(o[nf][2] * inv1, o[nf][3] * inv1);
        }
    }
}

// ---------------------------------------------------------------------------
extern "C" void kernel_launch(void* const* d_in, const int* in_sizes, int n_in,
                              void* d_out, int out_size)
{
    (void)in_sizes; (void)n_in; (void)out_size;
    const float* x  = (const float*)d_in[0];
    const float* Wk = (const float*)d_in[1];
    const float* Wq = (const float*)d_in[2];
    const float* Wv = (const float*)d_in[3];
    const float* Wp = (const float*)d_in[4];
    const float* bp = (const float*)d_in[5];
    float* out = (float*)d_out;

    cudaFuncSetAttribute(flash_kernel, cudaFuncAttributeMaxDynamicSharedMemorySize,
                         FLASH_SMEM);
    cudaFuncSetAttribute(qkv_gemm, cudaFuncAttributeMaxDynamicSharedMemorySize,
                         GEMM_SMEM);
    cudaFuncSetAttribute(proj_gemm, cudaFuncAttributeMaxDynamicSharedMemorySize,
                         GEMM_SMEM);

    conv_all<<<CONV_BLOCKS, 256>>>(x, Wq, Wk, Wv, Wp);
    qkv_gemm<<<dim3(CCH/128, MTOK/128, 3), GTHREADS, GEMM_SMEM>>>();
    flash_kernel<<<dim3(TSEQ/128, BATCH*NH), 256, FLASH_SMEM>>>();
    proj_gemm<<<dim3(CCH/128, MTOK/128), GTHREADS, GEMM_SMEM>>>(bp, out);
}

// round 16
// speedup vs baseline: 1.2919x; 1.2919x over previous
#include <cuda_runtime.h>
#include <cuda_fp16.h>
#include <math.h>
#include <stdint.h>

#define BATCH 4
#define TSEQ  2048
#define CCH   1024
#define NH    16
#define HS    64
#define MTOK  (BATCH*TSEQ)   // 8192
#define CC2   (CCH*CCH)

// ---------------------------------------------------------------------------
// Device-global scratch (fp16)
// ---------------------------------------------------------------------------
__device__ __half g_xh[MTOK*CCH];          // x, fp16
__device__ __half g_wh[4*CC2];             // Wq, Wk, Wv, Wp fp16
__device__ __half g_q[BATCH*NH*TSEQ*HS];   // [bh][t][d], PRE-SCALED by 0.125*log2e
__device__ __half g_k[BATCH*NH*TSEQ*HS];   // [bh][t][d]
__device__ __half g_vt[BATCH*NH*HS*TSEQ];  // [bh][d][t]  (TRANSPOSED)
__device__ __half g_att[MTOK*CCH];         // [b][t][c]

// ---------------------------------------------------------------------------
// Helpers
// ---------------------------------------------------------------------------
__device__ __forceinline__ void mma16(float* d,
                                      uint32_t a0, uint32_t a1, uint32_t a2, uint32_t a3,
                                      uint32_t b0, uint32_t b1)
{
    asm("mma.sync.aligned.m16n8k16.row.col.f32.f16.f16.f32 "
        "{%0,%1,%2,%3}, {%4,%5,%6,%7}, {%8,%9}, {%0,%1,%2,%3};\n"
        : "+f"(d[0]), "+f"(d[1]), "+f"(d[2]), "+f"(d[3])
        : "r"(a0), "r"(a1), "r"(a2), "r"(a3), "r"(b0), "r"(b1));
}

__device__ __forceinline__ void ldsm4(uint32_t* d, uint32_t addr) {
    asm volatile("ldmatrix.sync.aligned.m8n8.x4.shared.b16 {%0,%1,%2,%3}, [%4];"
        : "=r"(d[0]), "=r"(d[1]), "=r"(d[2]), "=r"(d[3]) : "r"(addr));
}

__device__ __forceinline__ float ex2(float x) {
    float y;
    asm("ex2.approx.f32 %0, %1;" : "=f"(y) : "f"(x));
    return y;
}

__device__ __forceinline__ uint32_t smem_u32(const void* p) {
    uint32_t a;
    asm("{ .reg .u64 t; cvta.to.shared.u64 t, %1; cvt.u32.u64 %0, t; }"
        : "=r"(a) : "l"(p));
    return a;
}

__device__ __forceinline__ void cpa16(uint32_t dst, const void* src) {
    asm volatile("cp.async.cg.shared.global [%0], [%1], 16;" :: "r"(dst), "l"(src));
}
__device__ __forceinline__ void cpa_commit() {
    asm volatile("cp.async.commit_group;" ::: "memory");
}
#define CPA_WAIT(N) asm volatile("cp.async.wait_group %0;" :: "n"(N) : "memory")

__device__ __forceinline__ uint32_t h2u(__half2 h) {
    return *(uint32_t*)&h;
}

#define QSCALE 0.180336881f      // 0.125 * log2(e)

// ---------------------------------------------------------------------------
// fp16 converter: x + all 4 weights, 4 float4s per thread (MLP=4)
// ---------------------------------------------------------------------------
#define XF4 (MTOK*CCH/4)         // 2,097,152
#define WF4 (CC2/4)              // 262,144
#define CF4 (XF4 + 4*WF4)        // 3,145,728 total float4s
#define CONV_BLOCKS (CF4/(256*4))

__global__ void __launch_bounds__(256) conv_all(const float* __restrict__ x,
                                                const float* __restrict__ wq,
                                                const float* __restrict__ wk,
                                                const float* __restrict__ wv,
                                                const float* __restrict__ wp)
{
    const int base = blockIdx.x * (256*4) + threadIdx.x;
    #pragma unroll
    for (int t = 0; t < 4; t++) {
        const int i = base + t * 256;
        float4 v;
        __half2* dst;
        if (i < XF4) {
            v = ((const float4*)x)[i];
            dst = (__half2*)g_xh + 2 * (size_t)i;
        } else {
            const int j = i - XF4;
            const int z = j / WF4;
            const int k = j - z * WF4;
            const float* s = (z == 0) ? wq : (z == 1) ? wk : (z == 2) ? wv : wp;
            v = ((const float4*)s)[k];
            dst = (__half2*)(g_wh + (size_t)z * CC2) + 2 * (size_t)k;
        }
        dst[0] = __floats2half2_rn(v.x, v.y);
        dst[1] = __floats2half2_rn(v.z, v.w);
    }
}

// ---------------------------------------------------------------------------
// fp16 GEMM core (R12 proven): BK=64, 2-stage cp.async, 128 threads = 4 warps
// 2x2, warp tile 64x64, ldmatrix frags, 72KB smem -> 3 CTAs/SM.
// ---------------------------------------------------------------------------
#define BKH      64
#define GSTW     36
#define GSTGW    (128*GSTW)             // 4608 words per operand-stage
#define NSTG     2
#define GEMM_SMEM (NSTG*2*GSTGW*4)      // 73728 bytes

__device__ __forceinline__ void gemm_core(const __half* __restrict__ A,
                                          const __half* __restrict__ B,
                                          float acc[4][8][4])
{
    extern __shared__ uint32_t smw[];
    uint32_t* As = smw;
    uint32_t* Bs = smw + NSTG*GSTGW;
    const uint32_t a_base = smem_u32(As);
    const uint32_t b_base = smem_u32(Bs);

    const int tid  = threadIdx.x;
    const int lane = tid & 31;
    const int warp = tid >> 5;
    const int wm   = warp >> 1;
    const int wn   = warp & 1;
    const int mb   = wm * 64;
    const int nb   = wn * 64;

    const int arow = (lane & 7) + ((lane >> 3) & 1) * 8;
    const int akw  = ((lane >> 4) & 1) * 4;
    const int brow = (lane & 7) + ((lane >> 4) & 1) * 8;
    const int bkw  = ((lane >> 3) & 1) * 4;

    const int lrow = tid >> 3;          // 0..15
    const int lc   = tid & 7;

    const __half* Ap = A + (size_t)lrow * CCH + lc * 8;
    const __half* Bp = B + (size_t)lrow * CCH + lc * 8;

    auto load_stage = [&](int s, int chunk) {
        const uint32_t ad = a_base + (uint32_t)s * (GSTGW*4) + (uint32_t)lrow * (GSTW*4) + lc * 16;
        const uint32_t bd = b_base + (uint32_t)s * (GSTGW*4) + (uint32_t)lrow * (GSTW*4) + lc * 16;
        const size_t go = (size_t)chunk * BKH;
        #pragma unroll
        for (int t = 0; t < 8; t++) {
            cpa16(ad + t * 16 * (GSTW*4), Ap + go + (size_t)t * 16 * CCH);
            cpa16(bd + t * 16 * (GSTW*4), Bp + go + (size_t)t * 16 * CCH);
        }
        cpa_commit();
    };

    load_stage(0, 0);

    const int NIT = CCH / BKH;          // 16
    for (int it = 0; it < NIT; it++) {
        CPA_WAIT(0);
        __syncthreads();

        if (it + 1 < NIT) load_stage((it + 1) & 1, it + 1);

        const uint32_t as_addr = a_base + (uint32_t)(it & 1) * (GSTGW*4);
        const uint32_t bs_addr = b_base + (uint32_t)(it & 1) * (GSTGW*4);

        #pragma unroll
        for (int ks = 0; ks < 4; ks++) {        // 4 x k16 per BK=64
            const int kk = ks * 8;
            uint32_t a[4][4], bfr[4][4];
            #pragma unroll
            for (int mf = 0; mf < 4; mf++)
                ldsm4(a[mf], as_addr + ((uint32_t)(mb + mf*16 + arow) * GSTW + kk + akw) * 4);
            #pragma unroll
            for (int pf = 0; pf < 4; pf++)
                ldsm4(bfr[pf], bs_addr + ((uint32_t)(nb + pf*16 + brow) * GSTW + kk + bkw) * 4);
            #pragma unroll
            for (int mf = 0; mf < 4; mf++)
                #pragma unroll
                for (int nf = 0; nf < 8; nf++)
                    mma16(acc[mf][nf], a[mf][0], a[mf][1], a[mf][2], a[mf][3],
                          bfr[nf >> 1][(nf & 1) * 2], bfr[nf >> 1][(nf & 1) * 2 + 1]);
        }
    }
}

// ---------------------------------------------------------------------------
// QKV GEMM (R12): z=0 -> q (PRE-SCALED), z=1 -> k, z=2 -> v transposed
// ---------------------------------------------------------------------------
__global__ void __launch_bounds__(128, 3) qkv_gemm()
{
    const int z  = blockIdx.z;
    const int m0 = blockIdx.y * 128;
    const int n0 = blockIdx.x * 128;

    float acc[4][8][4];
    #pragma unroll
    for (int i = 0; i < 4; i++)
        #pragma unroll
        for (int j = 0; j < 8; j++)
            #pragma unroll
            for (int c = 0; c < 4; c++) acc[i][j][c] = 0.f;

    gemm_core(g_xh + (size_t)m0 * CCH,
              g_wh + (size_t)z * CC2 + (size_t)n0 * CCH, acc);

    const int lane = threadIdx.x & 31;
    const int warp = threadIdx.x >> 5;
    const int wm = warp >> 1, wn = warp & 1;
    const int g = lane >> 2, r = lane & 3;

    if (z < 2) {
        __half* out = (z == 0) ? g_q : g_k;
        const float sc = (z == 0) ? QSCALE : 1.0f;
        #pragma unroll
        for (int mf = 0; mf < 4; mf++) {
            const int row0 = m0 + wm * 64 + mf * 16 + g;
            #pragma unroll
            for (int nf = 0; nf < 8; nf++) {
                const int col = n0 + wn * 64 + nf * 8 + 2 * r;
                const int h = col >> 6, d = col & 63;
                {
                    const int b = row0 >> 11, t = row0 & 2047;
                    *(__half2*)&out[((size_t)(b * NH + h) * TSEQ + t) * HS + d] =
                        __floats2half2_rn(acc[mf][nf][0] * sc, acc[mf][nf][1] * sc);
                }
                {
                    const int row1 = row0 + 8;
                    const int b = row1 >> 11, t = row1 & 2047;
                    *(__half2*)&out[((size_t)(b * NH + h) * TSEQ + t) * HS + d] =
                        __floats2half2_rn(acc[mf][nf][2] * sc, acc[mf][nf][3] * sc);
                }
            }
        }
    } else {
        #pragma unroll
        for (int mf = 0; mf < 4; mf++) {
            const int row0 = m0 + wm * 64 + mf * 16 + g;
            const int b = row0 >> 11, t0 = row0 & 2047;
            #pragma unroll
            for (int nf = 0; nf < 8; nf++) {
                const int col = n0 + wn * 64 + nf * 8 + 2 * r;
                const int h = col >> 6, d = col & 63;
                __half* base = g_vt + ((size_t)(b * NH + h) * HS + d) * TSEQ;
                base[t0]            = __float2half_rn(acc[mf][nf][0]);
                base[TSEQ + t0]     = __float2half_rn(acc[mf][nf][1]);
                base[t0 + 8]        = __float2half_rn(acc[mf][nf][2]);
                base[TSEQ + t0 + 8] = __float2half_rn(acc[mf][nf][3]);
            }
        }
    }
}

// ---------------------------------------------------------------------------
// Output projection with M=64 tile: 1024 CTAs, 4 CTAs/SM -> 592 slots ->
// 2 waves at 86.5% efficiency (vs 57.7% with the 128-tile / 512-CTA grid).
// 128 threads = 4 warps 2(M)x2(N), warp tile 32x64, acc 64 regs.
// SMEM: A 64 rows + B 128 rows, 2 stages = 55296 B.
// ---------------------------------------------------------------------------
#define PASTG (64*GSTW)                  // 2304 words (A stage)
#define PBSTG (128*GSTW)                 // 4608 words (B stage)
#define PROJ_SMEM ((2*PASTG + 2*PBSTG)*4)  // 55296 bytes

__global__ void __launch_bounds__(128, 4) proj_gemm(const float* __restrict__ bp,
                                                    float* __restrict__ out)
{
    extern __shared__ uint32_t smw[];
    const uint32_t a_base = smem_u32(smw);
    const uint32_t b_base = a_base + 2*PASTG*4;

    const int m0 = blockIdx.y * 64;
    const int n0 = blockIdx.x * 128;
    const __half* A = g_att + (size_t)m0 * CCH;
    const __half* B = g_wh + (size_t)3 * CC2 + (size_t)n0 * CCH;

    const int tid  = threadIdx.x;
    const int lane = tid & 31;
    const int warp = tid >> 5;
    const int wm   = warp >> 1;         // 0..1
    const int wn   = warp & 1;          // 0..1
    const int mb   = wm * 32;
    const int nb   = wn * 64;

    const int arow = (lane & 7) + ((lane >> 3) & 1) * 8;
    const int akw  = ((lane >> 4) & 1) * 4;
    const int brow = (lane & 7) + ((lane >> 4) & 1) * 8;
    const int bkw  = ((lane >> 3) & 1) * 4;

    const int lrow = tid >> 3;          // 0..15
    const int lc   = tid & 7;

    const __half* Ap = A + (size_t)lrow * CCH + lc * 8;
    const __half* Bp = B + (size_t)lrow * CCH + lc * 8;

    auto load_stage = [&](int s, int chunk) {
        const uint32_t ad = a_base + (uint32_t)s * (PASTG*4) + (uint32_t)lrow * (GSTW*4) + lc * 16;
        const uint32_t bd = b_base + (uint32_t)s * (PBSTG*4) + (uint32_t)lrow * (GSTW*4) + lc * 16;
        const size_t go = (size_t)chunk * BKH;
        #pragma unroll
        for (int t = 0; t < 4; t++)     // A: 64 rows
            cpa16(ad + t * 16 * (GSTW*4), Ap + go + (size_t)t * 16 * CCH);
        #pragma unroll
        for (int t = 0; t < 8; t++)     // B: 128 rows
            cpa16(bd + t * 16 * (GSTW*4), Bp + go + (size_t)t * 16 * CCH);
        cpa_commit();
    };

    float acc[2][8][4];
    #pragma unroll
    for (int i = 0; i < 2; i++)
        #pragma unroll
        for (int j = 0; j < 8; j++)
            #pragma unroll
            for (int c = 0; c < 4; c++) acc[i][j][c] = 0.f;

    load_stage(0, 0);

    const int NIT = CCH / BKH;          // 16
    for (int it = 0; it < NIT; it++) {
        CPA_WAIT(0);
        __syncthreads();

        if (it + 1 < NIT) load_stage((it + 1) & 1, it + 1);

        const uint32_t as_addr = a_base + (uint32_t)(it & 1) * (PASTG*4);
        const uint32_t bs_addr = b_base + (uint32_t)(it & 1) * (PBSTG*4);

        #pragma unroll
        for (int ks = 0; ks < 4; ks++) {
            const int kk = ks * 8;
            uint32_t a[2][4], bfr[4][4];
            #pragma unroll
            for (int mf = 0; mf < 2; mf++)
                ldsm4(a[mf], as_addr + ((uint32_t)(mb + mf*16 + arow) * GSTW + kk + akw) * 4);
            #pragma unroll
            for (int pf = 0; pf < 4; pf++)
                ldsm4(bfr[pf], bs_addr + ((uint32_t)(nb + pf*16 + brow) * GSTW + kk + bkw) * 4);
            #pragma unroll
            for (int mf = 0; mf < 2; mf++)
                #pragma unroll
                for (int nf = 0; nf < 8; nf++)
                    mma16(acc[mf][nf], a[mf][0], a[mf][1], a[mf][2], a[mf][3],
                          bfr[nf >> 1][(nf & 1) * 2], bfr[nf >> 1][(nf & 1) * 2 + 1]);
        }
    }

    const int g = lane >> 2, r = lane & 3;
    #pragma unroll
    for (int mf = 0; mf < 2; mf++) {
        const int row0 = m0 + mb + mf * 16 + g;
        #pragma unroll
        for (int nf = 0; nf < 8; nf++) {
            const int col = n0 + nb + nf * 8 + 2 * r;
            const float b0 = bp[col], b1 = bp[col + 1];
            *(float2*)&out[(size_t)row0 * CCH + col] =
                make_float2(acc[mf][nf][0] + b0, acc[mf][nf][1] + b1);
            *(float2*)&out[(size_t)(row0 + 8) * CCH + col] =
                make_float2(acc[mf][nf][2] + b0, acc[mf][nf][3] + b1);
        }
    }
}

// ---------------------------------------------------------------------------
// Causal flash attention (R12 proven): 128 threads = 4 warps x 32 query rows,
// 128-key K/V tiles double-buffered, V LDSM hoisted, per-warp diag bound.
// ---------------------------------------------------------------------------
#define KSTRW 36
#define VSTRW 68
#define KBUF  (128*KSTRW)                 // 4608 words
#define VBUF  (64*VSTRW)                  // 4352 words
#define F4K   0
#define F4V   (2*KBUF)
#define FLASH_SMEM ((2*KBUF + 2*VBUF)*4)  // 71680 bytes
#define HONES 0x3C003C00u                 // half2(1.0, 1.0)

__global__ void __launch_bounds__(128, 3) flash_kernel()
{
    extern __shared__ uint32_t smw[];
    const uint32_t sbase = smem_u32(smw);

    const int tid  = threadIdx.x;
    const int lane = tid & 31;
    const int warp = tid >> 5;
    const int mb   = warp * 32;
    const int g    = lane >> 2;
    const int r    = lane & 3;

    const int krow = lane & 7;
    const int kkw  = (lane >> 3) * 4;
    const int brow = (lane & 7) + ((lane >> 4) & 1) * 8;
    const int bkw  = ((lane >> 3) & 1) * 4;

    const int qi = (int)gridDim.x - 1 - (int)blockIdx.x;   // heavy first
    const int bh = blockIdx.y;
    const int q0 = qi * 128;
    const __half* kbase = g_k  + (size_t)bh * TSEQ * HS;   // [t][d]
    const __half* vbase = g_vt + (size_t)bh * HS * TSEQ;   // [d][t]

    #pragma unroll
    for (int t = 0; t < 8; t++) {
        const int i = tid + t * 128;
        const int row = i >> 3, c = i & 7;
        cpa16(sbase + (F4K*4) + row * (KSTRW*4) + c * 16,
              kbase + (size_t)row * HS + c * 8);
    }
    #pragma unroll
    for (int t = 0; t < 8; t++) {
        const int i = tid + t * 128;
        const int row = i >> 4, c = i & 15;
        cpa16(sbase + (F4V*4) + row * (VSTRW*4) + c * 16,
              vbase + (size_t)row * TSEQ + c * 8);
    }
    cpa_commit();

    uint32_t q[2][4][4];
    {
        const uint32_t* gq = (const uint32_t*)g_q;
        #pragma unroll
        for (int mf = 0; mf < 2; mf++) {
            const int row = q0 + mb + mf * 16 + g;
            const uint32_t* q0p = gq + ((size_t)bh * TSEQ + row) * 32;
            const uint32_t* q1p = q0p + 8 * 32;
            #pragma unroll
            for (int st = 0; st < 4; st++) {
                q[mf][st][0] = q0p[st * 8 + r];
                q[mf][st][1] = q1p[st * 8 + r];
                q[mf][st][2] = q0p[st * 8 + 4 + r];
                q[mf][st][3] = q1p[st * 8 + 4 + r];
            }
        }
    }

    float o[2][8][4];
    #pragma unroll
    for (int i = 0; i < 2; i++)
        #pragma unroll
        for (int j = 0; j < 8; j++)
            #pragma unroll
            for (int c = 0; c < 4; c++) o[i][j][c] = 0.f;
    float lacc[2][4];
    #pragma unroll
    for (int i = 0; i < 2; i++)
        #pragma unroll
        for (int c = 0; c < 4; c++) lacc[i][c] = 0.f;

    uint32_t ksub = sbase + (uint32_t)F4K * 4;
    uint32_t vsub = sbase + (uint32_t)F4V * 4;

    auto group = [&](int jj, bool masked) {
        uint32_t vb[4][4];
        #pragma unroll
        for (int pf = 0; pf < 4; pf++)
            ldsm4(vb[pf], vsub + ((uint32_t)(pf*16 + brow) * VSTRW + 8*jj + bkw) * 4);

        float s[2][2][4];
        #pragma unroll
        for (int jh = 0; jh < 2; jh++) {
            uint32_t kb[2][4];
            const uint32_t ka = ksub + ((uint32_t)(16*jj + 8*jh + krow) * KSTRW + kkw) * 4;
            ldsm4(kb[0], ka);
            ldsm4(kb[1], ka + 16 * 4);
            #pragma unroll
            for (int mf = 0; mf < 2; mf++)
                #pragma unroll
                for (int c = 0; c < 4; c++) s[jh][mf][c] = 0.f;
            #pragma unroll
            for (int st = 0; st < 4; st++) {
                const uint32_t b0 = kb[st >> 1][(st & 1) * 2];
                const uint32_t b1 = kb[st >> 1][(st & 1) * 2 + 1];
                mma16(s[jh][0], q[0][st][0], q[0][st][1], q[0][st][2], q[0][st][3], b0, b1);
                mma16(s[jh][1], q[1][st][0], q[1][st][1], q[1][st][2], q[1][st][3], b0, b1);
            }
        }

        if (masked) {
            #pragma unroll
            for (int jh = 0; jh < 2; jh++) {
                const int colb = 16*jj + 8*jh + 2*r;
                #pragma unroll
                for (int mf = 0; mf < 2; mf++) {
                    const int rwa = mb + mf * 16 + g;
                    if (colb     > rwa    ) s[jh][mf][0] = -1e30f;
                    if (colb + 1 > rwa    ) s[jh][mf][1] = -1e30f;
                    if (colb     > rwa + 8) s[jh][mf][2] = -1e30f;
                    if (colb + 1 > rwa + 8) s[jh][mf][3] = -1e30f;
                }
            }
        }

        uint32_t pA[2][4];
        #pragma unroll
        for (int jh = 0; jh < 2; jh++)
            #pragma unroll
            for (int mf = 0; mf < 2; mf++) {
                const float e0 = ex2(s[jh][mf][0]);
                const float e1 = ex2(s[jh][mf][1]);
                const float e2 = ex2(s[jh][mf][2]);
                const float e3 = ex2(s[jh][mf][3]);
                pA[mf][jh*2    ] = h2u(__floats2half2_rn(e0, e1));
                pA[mf][jh*2 + 1] = h2u(__floats2half2_rn(e2, e3));
            }

        mma16(lacc[0], pA[0][0], pA[0][1], pA[0][2], pA[0][3], HONES, HONES);
        mma16(lacc[1], pA[1][0], pA[1][1], pA[1][2], pA[1][3], HONES, HONES);

        #pragma unroll
        for (int nf = 0; nf < 8; nf++) {
            const uint32_t b0 = vb[nf >> 1][(nf & 1) * 2];
            const uint32_t b1 = vb[nf >> 1][(nf & 1) * 2 + 1];
            mma16(o[0][nf], pA[0][0], pA[0][1], pA[0][2], pA[0][3], b0, b1);
            mma16(o[1][nf], pA[1][0], pA[1][1], pA[1][2], pA[1][3], b0, b1);
        }
    };

    const int nt = qi + 1;
    for (int kt = 0; kt < nt; kt++) {
        __syncthreads();

        if (kt + 1 < nt) {
            const int b1 = (kt + 1) & 1;
            const __half* kg = kbase + (size_t)(kt + 1) * 128 * HS;
            const __half* vg = vbase + (size_t)(kt + 1) * 128;
            #pragma unroll
            for (int t = 0; t < 8; t++) {
                const int i = tid + t * 128;
                const int row = i >> 3, c = i & 7;
                cpa16(sbase + (F4K + b1*KBUF)*4 + row * (KSTRW*4) + c * 16,
                      kg + (size_t)row * HS + c * 8);
            }
            #pragma unroll
            for (int t = 0; t < 8; t++) {
                const int i = tid + t * 128;
                const int row = i >> 4, c = i & 15;
                cpa16(sbase + (F4V + b1*VBUF)*4 + row * (VSTRW*4) + c * 16,
                      vg + (size_t)row * TSEQ + c * 8);
            }
            cpa_commit();
            CPA_WAIT(1);
        } else {
            CPA_WAIT(0);
        }
        __syncthreads();

        const int b = kt & 1;
        ksub = sbase + (uint32_t)(F4K + b*KBUF) * 4;
        vsub = sbase + (uint32_t)(F4V + b*VBUF) * 4;

        if (kt < qi) {
            #pragma unroll
            for (int jj = 0; jj < 8; jj++) group(jj, false);
        } else {
            const int jmax = 2 * warp + 2;
            for (int jj = 0; jj < jmax; jj++) group(jj, true);
        }
    }

    const int b = bh >> 4, h = bh & 15;
    #pragma unroll
    for (int mf = 0; mf < 2; mf++) {
        const int row = mb + mf * 16 + g;
        const float inv0 = 1.0f / lacc[mf][0];
        const float inv1 = 1.0f / lacc[mf][2];
        const int t0 = q0 + row, t1 = t0 + 8;
        #pragma unroll
        for (int nf = 0; nf < 8; nf++) {
            const int c = h * HS + nf * 8 + 2 * r;
            *(__half2*)&g_att[((size_t)b * TSEQ + t0) * CCH + c] =
                __floats2half2_rn(o[mf][nf][0] * inv0, o[mf][nf][1] * inv0);
            *(__half2*)&g_att[((size_t)b * TSEQ + t1) * CCH + c] =
                __floats2half2_rn(o[mf][nf][2] * inv1, o[mf][nf][3] * inv1);
        }
    }
}

// ---------------------------------------------------------------------------
extern "C" void kernel_launch(void* const* d_in, const int* in_sizes, int n_in,
                              void* d_out, int out_size)
{
    (void)in_sizes; (void)n_in; (void)out_size;
    const float* x  = (const float*)d_in[0];
    const float* Wk = (const float*)d_in[1];
    const float* Wq = (const float*)d_in[2];
    const float* Wv = (const float*)d_in[3];
    const float* Wp = (const float*)d_in[4];
    const float* bp = (const float*)d_in[5];
    float* out = (float*)d_out;

    cudaFuncSetAttribute(flash_kernel, cudaFuncAttributeMaxDynamicSharedMemorySize,
                         FLASH_SMEM);
    cudaFuncSetAttribute(qkv_gemm, cudaFuncAttributeMaxDynamicSharedMemorySize,
                         GEMM_SMEM);
    cudaFuncSetAttribute(proj_gemm, cudaFuncAttributeMaxDynamicSharedMemorySize,
                         PROJ_SMEM);

    conv_all<<<CONV_BLOCKS, 256>>>(x, Wq, Wk, Wv, Wp);
    qkv_gemm<<<dim3(CCH/128, MTOK/128, 3), 128, GEMM_SMEM>>>();
    flash_kernel<<<dim3(TSEQ/128, BATCH*NH), 128, FLASH_SMEM>>>();
    proj_gemm<<<dim3(CCH/128, MTOK/64), 128, PROJ_SMEM>>>(bp, out);
}